// round 13
// baseline (speedup 1.0000x reference)
#include <cuda_runtime.h>

// CrossNetwork: x_l = x0 * (x_l . W_l) + b_l + x_l, L=6 layers.
// Identity: x_l = alpha_l * x0 + sum_{i<l} b_i, with
//   d_l = x0 . W_l ; C_l = (sum_{i<l} b_i) . W_l
//   s_l = alpha_l * d_l + C_l ; alpha_{l+1} = alpha_l + s_l ; alpha_0 = 1
//   out = alpha_L * x0 + sum_i b_i
// ~256 MB HBM traffic.
// R11 lesson: fusion cost 48 regs -> occ 23% -> DRAM 54%. Fixed harness
// overhead is ~4.6us regardless of launch count, so two kernels are fine.
// R12: back to two kernels; cross goes ROWS=2 with a 16-slot pair-merge
// (v[16] not v[32], x regs halved) -> ~4 blocks/SM, occupancy ~50%.

#define D_DIM 2048
#define L_DIM 6
#define D_VEC (D_DIM / 4)      // 512 float4 per row
#define TPB   256
#define NWARP (TPB / 32)       // 8
#define ROWS  2                // rows per block
#define NVAL  (ROWS * L_DIM)   // 12 dot values
#define PRE_BLKS 4
#define PRE_TPB  128           // 4 blocks x 128 threads x 4 cols = 2048

__device__ float g_Cpart[PRE_BLKS][L_DIM];
__device__ float g_bsum[D_DIM];

// ---------------------------------------------------------------------------
// Kernel 1: vectorized precompute. Thread <-> 4 consecutive columns.
// ---------------------------------------------------------------------------
__global__ __launch_bounds__(PRE_TPB) void precompute_kernel(
    const float* __restrict__ W, const float* __restrict__ b)
{
    const int t = threadIdx.x;
    const int q = blockIdx.x * PRE_TPB + t;   // float4 index, 0..511

    const float4* W4 = reinterpret_cast<const float4*>(W);
    const float4* b4 = reinterpret_cast<const float4*>(b);

    float4 wv[L_DIM], bv[L_DIM];
#pragma unroll
    for (int l = 0; l < L_DIM; ++l) {
        wv[l] = __ldg(&W4[l * D_VEC + q]);
        bv[l] = __ldg(&b4[l * D_VEC + q]);
    }

    float pc[L_DIM];
    float4 pre = make_float4(0.f, 0.f, 0.f, 0.f);
#pragma unroll
    for (int l = 0; l < L_DIM; ++l) {
        pc[l] = pre.x * wv[l].x + pre.y * wv[l].y
              + pre.z * wv[l].z + pre.w * wv[l].w;
        pre.x += bv[l].x;  pre.y += bv[l].y;
        pre.z += bv[l].z;  pre.w += bv[l].w;
    }
    reinterpret_cast<float4*>(g_bsum)[q] = pre;

#pragma unroll
    for (int l = 0; l < L_DIM; ++l) {
#pragma unroll
        for (int o = 16; o > 0; o >>= 1)
            pc[l] += __shfl_xor_sync(0xffffffffu, pc[l], o);
    }
    __shared__ float sred[PRE_TPB / 32][L_DIM];
    const int warp = t >> 5, lane = t & 31;
    if (lane == 0) {
#pragma unroll
        for (int l = 0; l < L_DIM; ++l) sred[warp][l] = pc[l];
    }
    __syncthreads();
    if (warp == 0 && lane < L_DIM) {
        float c = 0.f;
#pragma unroll
        for (int w = 0; w < PRE_TPB / 32; ++w) c += sred[w][lane];
        g_Cpart[blockIdx.x][lane] = c;
    }
}

// ---------------------------------------------------------------------------
// Kernel 2: one block per 2-row tile. 16-slot merge, low regs, high occ.
// ---------------------------------------------------------------------------
__global__ __launch_bounds__(TPB) void cross_kernel(
    const float* __restrict__ x, const float* __restrict__ W,
    float* __restrict__ out)
{
    const int t = threadIdx.x;
    const int warp = t >> 5, lane = t & 31;

    const size_t base = (size_t)blockIdx.x * ROWS * D_VEC;
    const float4* x4 = reinterpret_cast<const float4*>(x) + base;

    // ---- Phase 0: all x loads upfront (4 independent LDG.128) -------------
    float4 xa[ROWS], xb[ROWS];
#pragma unroll
    for (int r = 0; r < ROWS; ++r) {
        xa[r] = __ldcs(&x4[r * D_VEC + t]);
        xb[r] = __ldcs(&x4[r * D_VEC + t + TPB]);
    }

    // ---- Phase 1: layer-outer dot accumulation into v[0..11], pad to 16 ---
    float v[16];
#pragma unroll
    for (int i = NVAL; i < 16; ++i) v[i] = 0.f;
#pragma unroll
    for (int l = 0; l < L_DIM; ++l) {
        const float4* w4 = reinterpret_cast<const float4*>(W) + l * D_VEC;
        const float4 wa = __ldg(&w4[t]);
        const float4 wb = __ldg(&w4[t + TPB]);
#pragma unroll
        for (int r = 0; r < ROWS; ++r) {
            v[r * L_DIM + l] =
                  xa[r].x * wa.x + xa[r].y * wa.y
                + xa[r].z * wa.z + xa[r].w * wa.w
                + xb[r].x * wb.x + xb[r].y * wb.y
                + xb[r].z * wb.z + xb[r].w * wb.w;
        }
    }

    // ---- 16-slot pair-merge reduction (31 shuffles total). -----------------
    // Step 1: fold lane-bit 16 with plain butterflies (16 shuffles).
#pragma unroll
    for (int i = 0; i < 16; ++i)
        v[i] += __shfl_xor_sync(0xffffffffu, v[i], 16);
    // Step 2: merge levels d=8..1 within 16-lane groups (15 shuffles).
    // End state: lane L (and L+16) holds the full block-warp sum of value L.
#pragma unroll
    for (int d = 8; d >= 1; d >>= 1) {
#pragma unroll
        for (int i = 0; i < d; ++i) {
            const float send = (lane & d) ? v[i] : v[i + d];
            const float got = __shfl_xor_sync(0xffffffffu, send, d);
            v[i] = ((lane & d) ? v[i + d] : v[i]) + got;
        }
    }

    __shared__ float sred[NWARP][16];
    __shared__ __align__(16) float sd[16];
    if (lane < NVAL) sred[warp][lane] = v[0];
    __syncthreads();

    // ---- Cross-warp: warp0 sums 8 partials per value (conflict-free). -----
    if (warp == 0 && lane < NVAL) {
        float acc = 0.f;
#pragma unroll
        for (int w = 0; w < NWARP; ++w) acc += sred[w][lane];
        sd[lane] = acc;
    }
    __syncthreads();

    // ---- Phase 2: broadcast 12 dots via 3 LDS.128, alphas, store. ---------
    const float4* sd4 = reinterpret_cast<const float4*>(sd);
    float ds[NVAL];
#pragma unroll
    for (int q = 0; q < NVAL / 4; ++q) {
        const float4 dv = sd4[q];
        ds[q * 4 + 0] = dv.x;  ds[q * 4 + 1] = dv.y;
        ds[q * 4 + 2] = dv.z;  ds[q * 4 + 3] = dv.w;
    }

    // Row-invariant epilogue data (L2-hit, loaded late to cut peak regs).
    float C[L_DIM];
#pragma unroll
    for (int l = 0; l < L_DIM; ++l) {
        float c = 0.f;
#pragma unroll
        for (int j = 0; j < PRE_BLKS; ++j) c += g_Cpart[j][l];
        C[l] = c;
    }
    const float4* bs4 = reinterpret_cast<const float4*>(g_bsum);
    const float4 ba = bs4[t];
    const float4 bb = bs4[t + TPB];

    float4* o4 = reinterpret_cast<float4*>(out) + base;
#pragma unroll
    for (int r = 0; r < ROWS; ++r) {
        float a = 1.f;
#pragma unroll
        for (int l = 0; l < L_DIM; ++l)
            a += a * ds[r * L_DIM + l] + C[l];

        float4 oa, ob;
        oa.x = a * xa[r].x + ba.x;  oa.y = a * xa[r].y + ba.y;
        oa.z = a * xa[r].z + ba.z;  oa.w = a * xa[r].w + ba.w;
        ob.x = a * xb[r].x + bb.x;  ob.y = a * xb[r].y + bb.y;
        ob.z = a * xb[r].z + bb.z;  ob.w = a * xb[r].w + bb.w;
        __stcs(&o4[r * D_VEC + t], oa);
        __stcs(&o4[r * D_VEC + t + TPB], ob);
    }
}

// ---------------------------------------------------------------------------
extern "C" void kernel_launch(void* const* d_in, const int* in_sizes, int n_in,
                              void* d_out, int out_size)
{
    const float* x = (const float*)d_in[0];   // [B, 2048]
    const float* W = (const float*)d_in[1];   // [6, 2048]
    const float* b = (const float*)d_in[2];   // [6, 2048]
    float* out = (float*)d_out;               // [B, 2048]

    const int B = in_sizes[0] / D_DIM;

    precompute_kernel<<<PRE_BLKS, PRE_TPB>>>(W, b);
    cross_kernel<<<B / ROWS, TPB>>>(x, W, out);
}

// round 14
// speedup vs baseline: 1.5225x; 1.5225x over previous
#include <cuda_runtime.h>

// CrossNetwork: x_l = x0 * (x_l . W_l) + b_l + x_l, L=6 layers.
// Identity: x_l = alpha_l * x0 + sum_{i<l} b_i, with
//   d_l = x0 . W_l ; C_l = (sum_{i<l} b_i) . W_l
//   s_l = alpha_l * d_l + C_l ; alpha_{l+1} = alpha_l + s_l ; alpha_0 = 1
//   out = alpha_L * x0 + sum_i b_i
// ~256 MB HBM traffic; cross runs near the LTS ceiling.
// R12 lesson: ROWS=2 doubled shuffles/row -> L1 80% -> regression. The
// l1tex-op budget rules: ROWS=4 + 32-slot pair-merge is optimal.
// R13: (a) prologue fused into ONE 512-thread block (bsum + fully-reduced
// g_C[6]) ~1.2us; (b) cross reads g_C AFTER the barrier (v[] dead) to cut
// live registers vs R10's early 24-load C fold.

#define D_DIM 2048
#define L_DIM 6
#define D_VEC (D_DIM / 4)      // 512 float4 per row
#define TPB   256
#define NWARP (TPB / 32)       // 8
#define ROWS  4                // rows per block
#define NVAL  (ROWS * L_DIM)   // 24 dot values
#define PRE_TPB 512            // one block, 1 float4 per thread

__device__ float g_C[L_DIM];
__device__ float g_bsum[D_DIM];

// ---------------------------------------------------------------------------
// Kernel 1: ONE block x 512 threads. Thread t owns float4 column-chunk t.
// Computes g_bsum and the fully reduced g_C[6]. ~1.2us.
// ---------------------------------------------------------------------------
__global__ __launch_bounds__(PRE_TPB) void precompute_kernel(
    const float* __restrict__ W, const float* __restrict__ b)
{
    const int t = threadIdx.x;                 // == float4 index, 0..511
    const float4* W4 = reinterpret_cast<const float4*>(W);
    const float4* b4 = reinterpret_cast<const float4*>(b);

    // 12 independent coalesced LDG.128 (MLP=12).
    float4 wv[L_DIM], bv[L_DIM];
#pragma unroll
    for (int l = 0; l < L_DIM; ++l) {
        wv[l] = __ldg(&W4[l * D_VEC + t]);
        bv[l] = __ldg(&b4[l * D_VEC + t]);
    }

    float pc[L_DIM];
    float4 pre = make_float4(0.f, 0.f, 0.f, 0.f);   // prefix of b_i, i < l
#pragma unroll
    for (int l = 0; l < L_DIM; ++l) {
        pc[l] = pre.x * wv[l].x + pre.y * wv[l].y
              + pre.z * wv[l].z + pre.w * wv[l].w;
        pre.x += bv[l].x;  pre.y += bv[l].y;
        pre.z += bv[l].z;  pre.w += bv[l].w;
    }
    reinterpret_cast<float4*>(g_bsum)[t] = pre;

    // Block-reduce the 6 C partials across 16 warps.
#pragma unroll
    for (int l = 0; l < L_DIM; ++l) {
#pragma unroll
        for (int o = 16; o > 0; o >>= 1)
            pc[l] += __shfl_xor_sync(0xffffffffu, pc[l], o);
    }
    __shared__ float sred[PRE_TPB / 32][L_DIM];
    const int warp = t >> 5, lane = t & 31;
    if (lane == 0) {
#pragma unroll
        for (int l = 0; l < L_DIM; ++l) sred[warp][l] = pc[l];
    }
    __syncthreads();
    if (warp == 0 && lane < L_DIM) {
        float c = 0.f;
#pragma unroll
        for (int w = 0; w < PRE_TPB / 32; ++w) c += sred[w][lane];
        g_C[lane] = c;
    }
}

// ---------------------------------------------------------------------------
// Kernel 2: one block per 4-row tile. Epilogue data loaded post-barrier.
// ---------------------------------------------------------------------------
__global__ __launch_bounds__(TPB) void cross_kernel(
    const float* __restrict__ x, const float* __restrict__ W,
    float* __restrict__ out)
{
    const int t = threadIdx.x;
    const int warp = t >> 5, lane = t & 31;

    const size_t base = (size_t)blockIdx.x * ROWS * D_VEC;
    const float4* x4 = reinterpret_cast<const float4*>(x) + base;

    // ---- Phase 0: all x loads upfront (8 independent LDG.128, MLP=8) ------
    float4 xa[ROWS], xb[ROWS];
#pragma unroll
    for (int r = 0; r < ROWS; ++r) {
        xa[r] = __ldcs(&x4[r * D_VEC + t]);
        xb[r] = __ldcs(&x4[r * D_VEC + t + TPB]);
    }

    // ---- Phase 1: layer-outer dot accumulation into v[0..23], pad to 32 ---
    float v[32];
#pragma unroll
    for (int i = NVAL; i < 32; ++i) v[i] = 0.f;
#pragma unroll
    for (int l = 0; l < L_DIM; ++l) {
        const float4* w4 = reinterpret_cast<const float4*>(W) + l * D_VEC;
        const float4 wa = __ldg(&w4[t]);
        const float4 wb = __ldg(&w4[t + TPB]);
#pragma unroll
        for (int r = 0; r < ROWS; ++r) {
            v[r * L_DIM + l] =
                  xa[r].x * wa.x + xa[r].y * wa.y
                + xa[r].z * wa.z + xa[r].w * wa.w
                + xb[r].x * wb.x + xb[r].y * wb.y
                + xb[r].z * wb.z + xb[r].w * wb.w;
        }
    }

    // ---- Batched pair-merge warp reduction: 31 shuffles for 32 sums. ------
#pragma unroll
    for (int d = 16; d >= 1; d >>= 1) {
#pragma unroll
        for (int i = 0; i < d; ++i) {
            const float send = (lane & d) ? v[i] : v[i + d];
            const float got = __shfl_xor_sync(0xffffffffu, send, d);
            v[i] = ((lane & d) ? v[i + d] : v[i]) + got;
        }
    }

    __shared__ float sred[NWARP][32];
    __shared__ __align__(16) float sd[32];
    if (lane < NVAL) sred[warp][lane] = v[0];
    __syncthreads();

    // ---- Cross-warp: warp0 sums 8 partials per value (conflict-free). -----
    if (warp == 0 && lane < NVAL) {
        float acc = 0.f;
#pragma unroll
        for (int w = 0; w < NWARP; ++w) acc += sred[w][lane];
        sd[lane] = acc;
    }
    __syncthreads();

    // ---- Phase 2 (v[] dead now): C, bsum, broadcast dots, alphas, store. --
    float C[L_DIM];
#pragma unroll
    for (int l = 0; l < L_DIM; ++l) C[l] = g_C[l];   // uniform L2 hits

    const float4* bs4 = reinterpret_cast<const float4*>(g_bsum);
    const float4 ba = bs4[t];
    const float4 bb = bs4[t + TPB];

    const float4* sd4 = reinterpret_cast<const float4*>(sd);
    float ds[NVAL];
#pragma unroll
    for (int q = 0; q < NVAL / 4; ++q) {
        const float4 dv = sd4[q];
        ds[q * 4 + 0] = dv.x;  ds[q * 4 + 1] = dv.y;
        ds[q * 4 + 2] = dv.z;  ds[q * 4 + 3] = dv.w;
    }

    float4* o4 = reinterpret_cast<float4*>(out) + base;
#pragma unroll
    for (int r = 0; r < ROWS; ++r) {
        float a = 1.f;
#pragma unroll
        for (int l = 0; l < L_DIM; ++l)
            a += a * ds[r * L_DIM + l] + C[l];

        float4 oa, ob;
        oa.x = a * xa[r].x + ba.x;  oa.y = a * xa[r].y + ba.y;
        oa.z = a * xa[r].z + ba.z;  oa.w = a * xa[r].w + ba.w;
        ob.x = a * xb[r].x + bb.x;  ob.y = a * xb[r].y + bb.y;
        ob.z = a * xb[r].z + bb.z;  ob.w = a * xb[r].w + bb.w;
        __stcs(&o4[r * D_VEC + t], oa);
        __stcs(&o4[r * D_VEC + t + TPB], ob);
    }
}

// ---------------------------------------------------------------------------
extern "C" void kernel_launch(void* const* d_in, const int* in_sizes, int n_in,
                              void* d_out, int out_size)
{
    const float* x = (const float*)d_in[0];   // [B, 2048]
    const float* W = (const float*)d_in[1];   // [6, 2048]
    const float* b = (const float*)d_in[2];   // [6, 2048]
    float* out = (float*)d_out;               // [B, 2048]

    const int B = in_sizes[0] / D_DIM;

    precompute_kernel<<<1, PRE_TPB>>>(W, b);
    cross_kernel<<<B / ROWS, TPB>>>(x, W, out);
}